// round 11
// baseline (speedup 1.0000x reference)
#include <cuda_runtime.h>
#include <cstdint>

// Upsample_72619307041391
// x: (32, 512, 512, 1) f32, kernel: (4,4) f32 -> out: (32, 1024, 1024, 1) f32
//
// out = conv1d_horiz( repeat2x2(x), kernel.flatten()[1x16], SAME(pad_left=7) )
// Collapsed: output row pairs (2r, 2r+1) identical; even output cols = 9-tap
// FIR on x (offsets -4..+4), odd cols = 8-tap FIR (offsets -3..+4).
//
// R11 = R10 (warp-autonomous TMA stores + L2 residency hints) with 2x bigger
// warp chunks: each lane covers 8 x-cols (4 LDG.128, 2x read amplification
// instead of 3x), each warp stages a contiguous 2KB half-row and fires two
// 2KB TMA bulk stores. Block covers 4 input rows; grid 4096.

#define W_IN    512
#define W_OUT   1024

__device__ __forceinline__ uint32_t smem_u32(const void* p) {
    uint32_t a;
    asm("{ .reg .u64 t; cvta.to.shared.u64 t, %1; cvt.u32.u64 %0, t; }"
        : "=r"(a) : "l"(p));
    return a;
}

__device__ __forceinline__ float4 ldg_resident(const float4* p, uint64_t pol) {
    float4 v;
    asm("ld.global.nc.L2::cache_hint.v4.f32 {%0,%1,%2,%3}, [%4], %5;"
        : "=f"(v.x), "=f"(v.y), "=f"(v.z), "=f"(v.w) : "l"(p), "l"(pol));
    return v;
}

__global__ __launch_bounds__(256)
void upfir_kernel(const float* __restrict__ x,
                  const float* __restrict__ ker,
                  float* __restrict__ out)
{
    // One private 2KB (512-float) slice per warp.
    __shared__ __align__(16) float swarp[8][512];

    const int lane = threadIdx.x & 31;
    const int w    = threadIdx.x >> 5;            // warp 0..7
    const int h    = w & 1;                       // half of the row
    const int base = blockIdx.x * 4;              // first input row of block
    const int row  = base + (w >> 1);             // n*512 + r

    // L2 policies: inputs evict_last (keep resident), outputs evict_first.
    uint64_t pol_keep, pol_stream;
    asm("createpolicy.fractional.L2::evict_last.b64 %0, 1.0;"  : "=l"(pol_keep));
    asm("createpolicy.fractional.L2::evict_first.b64 %0, 1.0;" : "=l"(pol_stream));

    // Lane L covers x cols c0..c0+7 (c0 = 256h + 8L) -> out cols 2c0..2c0+15.
    // Footprint x[c0-4 .. c0+11] = float4 indices g-1 .. g+2, g = 64h + 2L.
    const int g = 64 * h + 2 * lane;
    const float4* xr4 = reinterpret_cast<const float4*>(x + (size_t)row * W_IN);
    const float4 zero4 = make_float4(0.f, 0.f, 0.f, 0.f);
    float4 fa = (g > 0)    ? ldg_resident(xr4 + (g - 1), pol_keep) : zero4;
    float4 fb =              ldg_resident(xr4 + g,       pol_keep);
    float4 fc =              ldg_resident(xr4 + (g + 1), pol_keep);
    float4 fd = (g < 126)  ? ldg_resident(xr4 + (g + 2), pol_keep) : zero4;

    // FIR taps: 16 contiguous floats -> 4 vector loads (uniform broadcast).
    const float4* k4 = reinterpret_cast<const float4*>(ker);
    const float4 ka = ldg_resident(k4 + 0, pol_keep);
    const float4 kb = ldg_resident(k4 + 1, pol_keep);
    const float4 kc = ldg_resident(k4 + 2, pol_keep);
    const float4 kd = ldg_resident(k4 + 3, pol_keep);
    const float k[16] = { ka.x, ka.y, ka.z, ka.w,
                          kb.x, kb.y, kb.z, kb.w,
                          kc.x, kc.y, kc.z, kc.w,
                          kd.x, kd.y, kd.z, kd.w };

    // Combined phase weights.
    float se[9], so[8];
    se[0] = k[0];
    #pragma unroll
    for (int d = 1; d < 8; d++) se[d] = k[2*d - 1] + k[2*d];
    se[8] = k[15];
    #pragma unroll
    for (int d = 0; d < 8; d++) so[d] = k[2*d] + k[2*d + 1];

    float xs[20] = { fa.x, fa.y, fa.z, fa.w,
                     fb.x, fb.y, fb.z, fb.w,
                     fc.x, fc.y, fc.z, fc.w,
                     fd.x, fd.y, fd.z, fd.w,
                     0.f, 0.f, 0.f, 0.f };   // xs[16..19] unused guard
    // xs[j] = x[row, c0 - 4 + j], j = 0..15 (+4 spill never read: i+d <= 15? no)
    // Actually i+d max = 7+8 = 15 for even, 7+1+7=15 for odd -> xs[0..15] only.

    float e[8], o[8];
    #pragma unroll
    for (int i = 0; i < 8; i++) { e[i] = 0.f; o[i] = 0.f; }
    #pragma unroll
    for (int d = 0; d < 9; d++) {
        const float wgt = se[d];
        #pragma unroll
        for (int i = 0; i < 8; i++) e[i] = fmaf(wgt, xs[i + d], e[i]);
    }
    #pragma unroll
    for (int d = 0; d < 8; d++) {
        const float wgt = so[d];
        #pragma unroll
        for (int i = 0; i < 8; i++) o[i] = fmaf(wgt, xs[i + 1 + d], o[i]);
    }

    // Stage this lane's 16 contiguous out floats (cols 2c0 .. 2c0+15).
    float4* s = reinterpret_cast<float4*>(&swarp[w][16 * lane]);
    #pragma unroll
    for (int j = 0; j < 4; j++)
        s[j] = make_float4(e[2*j], o[2*j], e[2*j + 1], o[2*j + 1]);

    __syncwarp();

    // Lane 0 fires two 2KB bulk stores (rows 2r and 2r+1), evict_first policy.
    if (lane == 0) {
        asm volatile("fence.proxy.async.shared::cta;" ::: "memory");
        const int n = row >> 9;
        const int r = row & 511;
        float* dst = out + ((size_t)n * 1024 + 2 * (size_t)r) * W_OUT + 512 * (size_t)h;
        uint32_t src = smem_u32(&swarp[w][0]);
        asm volatile(
            "cp.async.bulk.global.shared::cta.bulk_group.L2::cache_hint"
            " [%0], [%1], %2, %3;"
            :: "l"(dst), "r"(src), "r"(512 * 4), "l"(pol_stream) : "memory");
        asm volatile(
            "cp.async.bulk.global.shared::cta.bulk_group.L2::cache_hint"
            " [%0], [%1], %2, %3;"
            :: "l"(dst + W_OUT), "r"(src), "r"(512 * 4), "l"(pol_stream) : "memory");
        asm volatile("cp.async.bulk.commit_group;" ::: "memory");
        // Completion before CTA exit (SMEM lifetime + visibility).
        asm volatile("cp.async.bulk.wait_group 0;" ::: "memory");
    }
}

extern "C" void kernel_launch(void* const* d_in, const int* in_sizes, int n_in,
                              void* d_out, int out_size)
{
    const float* x   = (const float*)d_in[0];   // 32*512*512
    const float* ker = (const float*)d_in[1];   // 16 floats (4x4 row-major)
    float* out = (float*)d_out;                 // 32*1024*1024

    dim3 grid(32 * 512 / 4);   // 4096 blocks, 4 input rows each
    dim3 block(256);
    upfir_kernel<<<grid, block>>>(x, ker, out);
}

// round 12
// speedup vs baseline: 1.0203x; 1.0203x over previous
#include <cuda_runtime.h>
#include <cstdint>

// Upsample_72619307041391
// x: (32, 512, 512, 1) f32, kernel: (4,4) f32 -> out: (32, 1024, 1024, 1) f32
//
// out = conv1d_horiz( repeat2x2(x), kernel.flatten()[1x16], SAME(pad_left=7) )
// Collapsed: output row pairs (2r, 2r+1) identical; even output cols = 9-tap
// FIR on x (offsets -4..+4), odd cols = 8-tap FIR (offsets -3..+4).
//
// R12 = R10 (warp-autonomous 1KB TMA stores + L2 residency hints) with the
// neighbor loads replaced by warp shuffles: each lane does ONE main LDG.128
// (read amplification 3x -> ~1x); halos come via shfl.up/down; only lanes
// 0/31 issue a predicated edge load.

#define W_IN    512
#define W_OUT   1024
#define TPR     128          // threads per x-row (512/4)

__device__ __forceinline__ uint32_t smem_u32(const void* p) {
    uint32_t a;
    asm("{ .reg .u64 t; cvta.to.shared.u64 t, %1; cvt.u32.u64 %0, t; }"
        : "=r"(a) : "l"(p));
    return a;
}

__device__ __forceinline__ float4 ldg_resident(const float4* p, uint64_t pol) {
    float4 v;
    asm("ld.global.nc.L2::cache_hint.v4.f32 {%0,%1,%2,%3}, [%4], %5;"
        : "=f"(v.x), "=f"(v.y), "=f"(v.z), "=f"(v.w) : "l"(p), "l"(pol));
    return v;
}

__global__ __launch_bounds__(256, 8)
void upfir_kernel(const float* __restrict__ x,
                  const float* __restrict__ ker,
                  float* __restrict__ out)
{
    // One private 1KB (256-float) slice per warp.
    __shared__ __align__(16) float swarp[8][256];

    const int lane = threadIdx.x & 31;
    const int w    = threadIdx.x >> 5;            // warp 0..7
    const int t    = threadIdx.x & (TPR - 1);     // 0..127 within row
    const int half = threadIdx.x >> 7;            // 0/1: which row of the pair
    const int q    = w & 3;                       // quarter of the row
    const int row  = blockIdx.x * 2 + half;       // n*512 + r

    // L2 policies: inputs evict_last (keep resident), outputs evict_first.
    uint64_t pol_keep, pol_stream;
    asm("createpolicy.fractional.L2::evict_last.b64 %0, 1.0;"  : "=l"(pol_keep));
    asm("createpolicy.fractional.L2::evict_first.b64 %0, 1.0;" : "=l"(pol_stream));

    const float4 zero4 = make_float4(0.f, 0.f, 0.f, 0.f);
    const float4* xr4 = reinterpret_cast<const float4*>(x + (size_t)row * W_IN);

    // Main load: own float4 only. Edge lanes fetch the out-of-warp halo.
    float4 b = ldg_resident(xr4 + t, pol_keep);
    float4 edge = zero4;
    if (lane == 0) {
        if (t > 0) edge = ldg_resident(xr4 + (t - 1), pol_keep);
    } else if (lane == 31) {
        if (t < TPR - 1) edge = ldg_resident(xr4 + (t + 1), pol_keep);
    }

    // FIR taps: 16 contiguous floats -> 4 vector loads (uniform broadcast).
    const float4* k4 = reinterpret_cast<const float4*>(ker);
    const float4 ka = ldg_resident(k4 + 0, pol_keep);
    const float4 kb = ldg_resident(k4 + 1, pol_keep);
    const float4 kc = ldg_resident(k4 + 2, pol_keep);
    const float4 kd = ldg_resident(k4 + 3, pol_keep);
    const float k[16] = { ka.x, ka.y, ka.z, ka.w,
                          kb.x, kb.y, kb.z, kb.w,
                          kc.x, kc.y, kc.z, kc.w,
                          kd.x, kd.y, kd.z, kd.w };

    // Combined phase weights.
    float se[9], so[8];
    se[0] = k[0];
    #pragma unroll
    for (int d = 1; d < 8; d++) se[d] = k[2*d - 1] + k[2*d];
    se[8] = k[15];
    #pragma unroll
    for (int d = 0; d < 8; d++) so[d] = k[2*d] + k[2*d + 1];

    // Halo via shuffles: a = lane-1's b, c = lane+1's b (edges overridden).
    float4 a, c;
    a.x = __shfl_up_sync(0xffffffffu, b.x, 1);
    a.y = __shfl_up_sync(0xffffffffu, b.y, 1);
    a.z = __shfl_up_sync(0xffffffffu, b.z, 1);
    a.w = __shfl_up_sync(0xffffffffu, b.w, 1);
    c.x = __shfl_down_sync(0xffffffffu, b.x, 1);
    c.y = __shfl_down_sync(0xffffffffu, b.y, 1);
    c.z = __shfl_down_sync(0xffffffffu, b.z, 1);
    c.w = __shfl_down_sync(0xffffffffu, b.w, 1);
    if (lane == 0)  a = edge;
    if (lane == 31) c = edge;

    float xs[12] = { a.x, a.y, a.z, a.w,
                     b.x, b.y, b.z, b.w,
                     c.x, c.y, c.z, c.w };

    float e0=0.f, e1=0.f, e2=0.f, e3=0.f;
    float o0=0.f, o1=0.f, o2=0.f, o3=0.f;
    #pragma unroll
    for (int d = 0; d < 9; d++) {
        const float wgt = se[d];
        e0 = fmaf(wgt, xs[d    ], e0);
        e1 = fmaf(wgt, xs[d + 1], e1);
        e2 = fmaf(wgt, xs[d + 2], e2);
        e3 = fmaf(wgt, xs[d + 3], e3);
    }
    #pragma unroll
    for (int d = 0; d < 8; d++) {
        const float wgt = so[d];
        o0 = fmaf(wgt, xs[d + 1], o0);
        o1 = fmaf(wgt, xs[d + 2], o1);
        o2 = fmaf(wgt, xs[d + 3], o2);
        o3 = fmaf(wgt, xs[d + 4], o3);
    }

    // Stage this warp's contiguous 1KB chunk (out cols 256q .. 256q+255).
    float4* s = reinterpret_cast<float4*>(&swarp[w][8 * lane]);
    s[0] = make_float4(e0, o0, e1, o1);
    s[1] = make_float4(e2, o2, e3, o3);

    __syncwarp();

    // Lane 0 fires two 1KB bulk stores (rows 2r and 2r+1), evict_first policy.
    if (lane == 0) {
        asm volatile("fence.proxy.async.shared::cta;" ::: "memory");
        const int n = row >> 9;
        const int r = row & 511;
        float* dst = out + ((size_t)n * 1024 + 2 * (size_t)r) * W_OUT + 256 * (size_t)q;
        uint32_t src = smem_u32(&swarp[w][0]);
        asm volatile(
            "cp.async.bulk.global.shared::cta.bulk_group.L2::cache_hint"
            " [%0], [%1], %2, %3;"
            :: "l"(dst), "r"(src), "r"(256 * 4), "l"(pol_stream) : "memory");
        asm volatile(
            "cp.async.bulk.global.shared::cta.bulk_group.L2::cache_hint"
            " [%0], [%1], %2, %3;"
            :: "l"(dst + W_OUT), "r"(src), "r"(256 * 4), "l"(pol_stream) : "memory");
        asm volatile("cp.async.bulk.commit_group;" ::: "memory");
        // Completion before CTA exit (SMEM lifetime + visibility).
        asm volatile("cp.async.bulk.wait_group 0;" ::: "memory");
    }
}

extern "C" void kernel_launch(void* const* d_in, const int* in_sizes, int n_in,
                              void* d_out, int out_size)
{
    const float* x   = (const float*)d_in[0];   // 32*512*512
    const float* ker = (const float*)d_in[1];   // 16 floats (4x4 row-major)
    float* out = (float*)d_out;                 // 32*1024*1024

    dim3 grid(32 * 512 / 2);   // 8192 blocks, 2 input rows each
    dim3 block(256);
    upfir_kernel<<<grid, block>>>(x, ker, out);
}